// round 4
// baseline (speedup 1.0000x reference)
#include <cuda_runtime.h>
#include <math.h>

// ---------------- problem dims ----------------
#define B_    512
#define T_    128
#define IDIM  512
#define N0    538
#define N1    358
#define N2    128
#define K0    1050     // IDIM + N0
#define K1    896      // N0 + N1
#define K2    486      // N1 + N2
#define KP0   1056     // K0 padded to 32
#define KP1   896
#define KP2   512
#define OUT_  128
#define UNITS 1024

// tile config
#define BM 128
#define BN 128
#define BK 32
#define LDK 36
#define LDC 132
#define SMEM_FLOATS (4*BM*LDK)       // As[2][128][36] + Bs[2][128][36] = 18432 floats
#define SMEM_BYTES  (SMEM_FLOATS*4)  // 73728 B (Cs staging 128*132=16896 floats fits)

#define NCTA 132                      // 68 (L0) + 48 (L1) + 16 (L2) tiles

// ---------------- scratch (device globals; no allocs allowed) ----------------
__device__ __align__(16) float g_W0[4 * N0 * KP0];
__device__ __align__(16) float g_W1[4 * N1 * KP1];
__device__ __align__(16) float g_W2[4 * N2 * KP2];
__device__ __align__(16) float g_bc0[4 * N0];
__device__ __align__(16) float g_bc1[4 * N1];
__device__ __align__(16) float g_bc2[4 * N2];
__device__ __align__(16) float g_h0[2][B_ * N0];
__device__ __align__(16) float g_h1[2][B_ * N1];
__device__ __align__(16) float g_h2[2][B_ * N2];
__device__ __align__(16) float g_motor[B_ * T_ * OUT_];
__device__ unsigned g_bar_count;
__device__ unsigned g_bar_release;

// ---------------- prep kernels ----------------
__global__ void build_w(const float* __restrict__ W1, const float* __restrict__ W2,
                        const float* __restrict__ Wa, const float* __restrict__ Wb,
                        const float* __restrict__ mask,
                        const float* __restrict__ b1, const float* __restrict__ b2,
                        const float* __restrict__ ba, const float* __restrict__ bb,
                        float* __restrict__ Wc, float* __restrict__ bc,
                        int n, int K, int KP)
{
    int idx = blockIdx.x * blockDim.x + threadIdx.x;
    int tot = 4 * n * KP;
    if (idx < tot) {
        int row = idx / KP, k = idx - row * KP;
        float v = 0.f;
        if (k < K) {
            int j = row >> 2, g = row & 3;
            if (g == 0)      v = W1[j * K + k] * mask[j * K + k];
            else if (g == 1) v = W2[j * K + k] * mask[j * K + k];
            else if (g == 2) v = Wa[j * K + k];
            else             v = Wb[j * K + k];
        }
        Wc[idx] = v;
    }
    if (idx < 4 * n) {
        int j = idx >> 2, g = idx & 3;
        bc[idx] = (g == 0) ? b1[j] : (g == 1) ? b2[j] : (g == 2) ? ba[j] : bb[j];
    }
}

__global__ void init_h(const float* __restrict__ h0in)
{
    int idx = blockIdx.x * blockDim.x + threadIdx.x;
    if (idx >= B_ * UNITS) return;
    int b = idx / UNITS, c = idx - b * UNITS;
    float v = h0in[idx];
    if (c < N0)           g_h0[0][b * N0 + c] = v;
    else if (c < N0 + N1) g_h1[0][b * N1 + (c - N0)] = v;
    else                  g_h2[0][b * N2 + (c - N0 - N1)] = v;
}

__global__ void write_hn(float* __restrict__ out)
{
    int idx = blockIdx.x * blockDim.x + threadIdx.x;
    if (idx >= B_ * UNITS) return;
    int b = idx / UNITS, c = idx - b * UNITS;
    float v;
    if (c < N0)           v = g_h0[0][b * N0 + c];
    else if (c < N0 + N1) v = g_h1[0][b * N1 + (c - N0)];
    else                  v = g_h2[0][b * N2 + (c - N0 - N1)];
    out[idx] = v;
}

__global__ void reset_bar() { g_bar_count = 0; g_bar_release = 0; }

// ---------------- helpers ----------------
__device__ __forceinline__ float f2tf32(float f) {
    unsigned r;
    asm("cvt.rna.tf32.f32 %0, %1;" : "=r"(r) : "f"(f));
    return __uint_as_float(r);
}

__device__ __forceinline__ void mma_tf32(float& c0, float& c1, float& c2, float& c3,
                                         unsigned a0, unsigned a1, unsigned a2, unsigned a3,
                                         unsigned b0, unsigned b1)
{
    asm volatile("mma.sync.aligned.m16n8k8.row.col.f32.tf32.tf32.f32 "
                 "{%0,%1,%2,%3}, {%4,%5,%6,%7}, {%8,%9}, {%0,%1,%2,%3};"
                 : "+f"(c0), "+f"(c1), "+f"(c2), "+f"(c3)
                 : "r"(a0), "r"(a1), "r"(a2), "r"(a3), "r"(b0), "r"(b1));
}

__device__ __forceinline__ void grid_bar(int epoch)
{
    __syncthreads();
    if (threadIdx.x == 0) {
        __threadfence();
        unsigned a = atomicAdd(&g_bar_count, 1u) + 1u;
        if (a == (unsigned)(NCTA * epoch)) {
            asm volatile("st.global.release.gpu.u32 [%0], %1;"
                         :: "l"(&g_bar_release), "r"((unsigned)epoch) : "memory");
        } else {
            unsigned r;
            do {
                asm volatile("ld.global.acquire.gpu.u32 %0, [%1];"
                             : "=r"(r) : "l"(&g_bar_release) : "memory");
            } while (r < (unsigned)epoch);
        }
    }
    __syncthreads();
}

// ---------------- one 128x128 GEMM tile + fused CfC gate ----------------
// C = act( A @ W^T + bias ); logical A row m: A1[m,k] for k<k1 else A2[m,k-k1]
// W row-major (Nout, KP), zero-padded on [Ktot, KP).
template <bool GATED>
__device__ __forceinline__ void cell_tile(
    const float* __restrict__ A1, int lda1, int k1,
    const float* __restrict__ A2, int lda2, int Ktot, int KP,
    const float* __restrict__ W, const float* __restrict__ bias,
    int Nout, int nUnits,
    float* __restrict__ Cmain, int ldcm,
    float* __restrict__ Caux, int ldca,
    int m0, int n0, float* sm)
{
    float* As = sm;                       // [2][BM][LDK]
    float* Bs = sm + 2 * BM * LDK;        // [2][BN][LDK]

    const int tid  = threadIdx.x;
    const int lane = tid & 31;
    const int g    = lane >> 2;
    const int tk   = lane & 3;
    const int wid  = tid >> 5;
    const int wm   = wid & 1;             // 2 warps in M  -> 64 rows each
    const int wn   = wid >> 1;            // 4 warps in N  -> 32 cols each

    const int lK  = tid & 31;             // A load: column in BK
    const int arb = tid >> 5;             // A load: row base (stride 8)
    const int bkg = (tid & 7) * 4;        // B load: k group (float4)
    const int bnb = tid >> 3;             // B load: n base (stride 32)

    float acc[4][4][4];
    #pragma unroll
    for (int mt = 0; mt < 4; mt++)
        #pragma unroll
        for (int nt = 0; nt < 4; nt++)
            #pragma unroll
            for (int i = 0; i < 4; i++) acc[mt][nt][i] = 0.f;

    const int nkt = KP / BK;
    float  areg[16];
    float4 breg[4];

    auto ldg = [&](int kt) {
        int k = kt * BK + lK;
        #pragma unroll
        for (int r = 0; r < 16; r++) {
            int row = m0 + arb + r * 8;
            float v = 0.f;
            if (k < Ktot)
                v = (k < k1) ? A1[(long)row * lda1 + k]
                             : A2[(long)row * lda2 + (k - k1)];
            areg[r] = v;
        }
        int kb = kt * BK + bkg;
        #pragma unroll
        for (int r = 0; r < 4; r++) {
            int n = n0 + bnb + r * 32;
            float4 v = make_float4(0.f, 0.f, 0.f, 0.f);
            if (n < Nout) v = *(const float4*)(W + (long)n * KP + kb);
            breg[r] = v;
        }
    };
    auto sts = [&](int buf) {
        float* a = As + buf * BM * LDK;
        float* b = Bs + buf * BM * LDK;
        #pragma unroll
        for (int r = 0; r < 16; r++) a[(arb + r * 8) * LDK + lK] = f2tf32(areg[r]);
        #pragma unroll
        for (int r = 0; r < 4; r++) {
            float4 v = breg[r];
            v.x = f2tf32(v.x); v.y = f2tf32(v.y); v.z = f2tf32(v.z); v.w = f2tf32(v.w);
            *(float4*)(b + (bnb + r * 32) * LDK + bkg) = v;
        }
    };

    ldg(0);
    sts(0);
    __syncthreads();

    for (int kt = 0; kt < nkt; kt++) {
        if (kt + 1 < nkt) ldg(kt + 1);

        const float* a = As + (kt & 1) * BM * LDK;
        const float* b = Bs + (kt & 1) * BM * LDK;
        #pragma unroll
        for (int ks = 0; ks < BK; ks += 8) {
            unsigned af[4][4], bf[4][2];
            #pragma unroll
            for (int mt = 0; mt < 4; mt++) {
                int row = wm * 64 + mt * 16 + g;
                af[mt][0] = __float_as_uint(a[row * LDK + ks + tk]);
                af[mt][1] = __float_as_uint(a[(row + 8) * LDK + ks + tk]);
                af[mt][2] = __float_as_uint(a[row * LDK + ks + tk + 4]);
                af[mt][3] = __float_as_uint(a[(row + 8) * LDK + ks + tk + 4]);
            }
            #pragma unroll
            for (int nt = 0; nt < 4; nt++) {
                int n = wn * 32 + nt * 8 + g;
                bf[nt][0] = __float_as_uint(b[n * LDK + ks + tk]);
                bf[nt][1] = __float_as_uint(b[n * LDK + ks + tk + 4]);
            }
            #pragma unroll
            for (int mt = 0; mt < 4; mt++)
                #pragma unroll
                for (int nt = 0; nt < 4; nt++)
                    mma_tf32(acc[mt][nt][0], acc[mt][nt][1], acc[mt][nt][2], acc[mt][nt][3],
                             af[mt][0], af[mt][1], af[mt][2], af[mt][3],
                             bf[nt][0], bf[nt][1]);
        }

        if (kt + 1 < nkt) {
            sts((kt + 1) & 1);
            __syncthreads();
        }
    }

    // ---- epilogue: stage C in smem (aliases A/B buffers) ----
    __syncthreads();
    float* Cs = sm;                       // [BM][LDC]
    #pragma unroll
    for (int mt = 0; mt < 4; mt++) {
        int row = wm * 64 + mt * 16 + g;
        #pragma unroll
        for (int nt = 0; nt < 4; nt++) {
            int col = wn * 32 + nt * 8 + 2 * tk;
            Cs[row * LDC + col]           = acc[mt][nt][0];
            Cs[row * LDC + col + 1]       = acc[mt][nt][1];
            Cs[(row + 8) * LDC + col]     = acc[mt][nt][2];
            Cs[(row + 8) * LDC + col + 1] = acc[mt][nt][3];
        }
    }
    __syncthreads();

    if (GATED) {
        int ul = tid & 31;
        int u  = (n0 >> 2) + ul;
        if (u < nUnits) {
            float4 bb = *(const float4*)(bias + 4 * u);
            #pragma unroll
            for (int r = 0; r < 16; r++) {
                int row = (tid >> 5) + 8 * r;
                float4 v = *(const float4*)(Cs + row * LDC + 4 * ul);
                float ff1 = tanhf(v.x + bb.x);
                float ff2 = tanhf(v.y + bb.y);
                float s   = (v.z + bb.z) + (v.w + bb.w);
                float tg  = 1.f / (1.f + __expf(-s));
                float h   = ff1 + tg * (ff2 - ff1);
                long grow = m0 + row;
                Cmain[grow * ldcm + u] = h;
                if (Caux) Caux[grow * ldca + u] = h;
            }
        }
    } else {
        int ul  = tid & 31;
        int col = n0 + 4 * ul;
        if (col < Nout) {
            float4 bb = *(const float4*)(bias + col);
            #pragma unroll
            for (int r = 0; r < 16; r++) {
                int row = (tid >> 5) + 8 * r;
                float4 v = *(const float4*)(Cs + row * LDC + 4 * ul);
                v.x += bb.x; v.y += bb.y; v.z += bb.z; v.w += bb.w;
                *(float4*)(Cmain + (long)(m0 + row) * ldcm + col) = v;
            }
        }
    }
    __syncthreads();   // protect smem before next phase reuses it
}

// ---------------- persistent wavefront kernel ----------------
// phase p: L0 computes step p, L1 step p-1, L2 step p-2; one grid barrier per phase.
__global__ __launch_bounds__(256, 1)
void rnn_persistent(const float* __restrict__ x)
{
    extern __shared__ float sm[];
    const int bid = blockIdx.x;

    for (int p = 0; p < T_ + 2; p++) {
        if (bid < 68) {                       // layer 0: 4 x 17 tiles
            int t = p;
            if (t < T_) {
                int row = bid & 3, col = bid >> 2;
                int rp = t & 1, wp = 1 - rp;
                cell_tile<true>(x + (long)t * IDIM, T_ * IDIM, IDIM,
                                g_h0[rp], N0, K0, KP0,
                                g_W0, g_bc0, 4 * N0, N0,
                                g_h0[wp], N0, nullptr, 0,
                                row * BM, col * BN, sm);
            }
        } else if (bid < 116) {               // layer 1: 4 x 12 tiles
            int t = p - 1;
            if (t >= 0 && t < T_) {
                int b = bid - 68;
                int row = b & 3, col = b >> 2;
                int rp = t & 1, wp = 1 - rp;
                cell_tile<true>(g_h0[wp], N0, N0,      // h0 after step t lives in buffer wp
                                g_h1[rp], N1, K1, KP1,
                                g_W1, g_bc1, 4 * N1, N1,
                                g_h1[wp], N1, nullptr, 0,
                                row * BM, col * BN, sm);
            }
        } else {                              // layer 2: 4 x 4 tiles
            int t = p - 2;
            if (t >= 0 && t < T_) {
                int b = bid - 116;
                int row = b & 3, col = b >> 2;
                int rp = t & 1, wp = 1 - rp;
                cell_tile<true>(g_h1[wp], N1, N1,
                                g_h2[rp], N2, K2, KP2,
                                g_W2, g_bc2, 4 * N2, N2,
                                g_h2[wp], N2,
                                g_motor + (long)t * OUT_, T_ * OUT_,
                                row * BM, col * BN, sm);
            }
        }
        grid_bar(p + 1);
    }
}

// ---------------- final FC: pred = motor @ Wfc^T + bfc ----------------
__global__ __launch_bounds__(256)
void fc_kernel(float* __restrict__ pred, const float* __restrict__ Wfc,
               const float* __restrict__ bfc)
{
    extern __shared__ float sm[];
    cell_tile<false>(g_motor, OUT_, OUT_,
                     g_motor, OUT_, OUT_, 128,
                     Wfc, bfc, OUT_, 0,
                     pred, OUT_, nullptr, 0,
                     blockIdx.x * BM, 0, sm);
}

// ---------------- launcher ----------------
extern "C" void kernel_launch(void* const* d_in, const int* in_sizes, int n_in,
                              void* d_out, int out_size)
{
    (void)in_sizes; (void)n_in; (void)out_size;
    const float* x    = (const float*)d_in[0];
    const float* h0in = (const float*)d_in[1];
    const float* mask[3]  = { (const float*)d_in[2],  (const float*)d_in[11], (const float*)d_in[20] };
    const float* Wff1[3]  = { (const float*)d_in[3],  (const float*)d_in[12], (const float*)d_in[21] };
    const float* Wff2[3]  = { (const float*)d_in[4],  (const float*)d_in[13], (const float*)d_in[22] };
    const float* Wta[3]   = { (const float*)d_in[5],  (const float*)d_in[14], (const float*)d_in[23] };
    const float* Wtb[3]   = { (const float*)d_in[6],  (const float*)d_in[15], (const float*)d_in[24] };
    const float* bff1[3]  = { (const float*)d_in[7],  (const float*)d_in[16], (const float*)d_in[25] };
    const float* bff2[3]  = { (const float*)d_in[8],  (const float*)d_in[17], (const float*)d_in[26] };
    const float* bta[3]   = { (const float*)d_in[9],  (const float*)d_in[18], (const float*)d_in[27] };
    const float* btb[3]   = { (const float*)d_in[10], (const float*)d_in[19], (const float*)d_in[28] };
    const float* Wfc = (const float*)d_in[29];
    const float* bfc = (const float*)d_in[30];

    float* out  = (float*)d_out;
    float* pred = out;
    float* hn   = out + (long)B_ * T_ * OUT_;

    float* dW[3]; float* dbc[3];
    cudaGetSymbolAddress((void**)&dW[0], g_W0);
    cudaGetSymbolAddress((void**)&dW[1], g_W1);
    cudaGetSymbolAddress((void**)&dW[2], g_W2);
    cudaGetSymbolAddress((void**)&dbc[0], g_bc0);
    cudaGetSymbolAddress((void**)&dbc[1], g_bc1);
    cudaGetSymbolAddress((void**)&dbc[2], g_bc2);

    cudaFuncSetAttribute(rnn_persistent, cudaFuncAttributeMaxDynamicSharedMemorySize, SMEM_BYTES);
    cudaFuncSetAttribute(fc_kernel,      cudaFuncAttributeMaxDynamicSharedMemorySize, SMEM_BYTES);

    const int nL[3] = { N0, N1, N2 };
    const int kL[3] = { K0, K1, K2 };
    const int kP[3] = { KP0, KP1, KP2 };

    for (int l = 0; l < 3; l++) {
        int tot = 4 * nL[l] * kP[l];
        build_w<<<(tot + 255) / 256, 256>>>(Wff1[l], Wff2[l], Wta[l], Wtb[l], mask[l],
                                            bff1[l], bff2[l], bta[l], btb[l],
                                            dW[l], dbc[l], nL[l], kL[l], kP[l]);
    }
    init_h<<<(B_ * UNITS + 255) / 256, 256>>>(h0in);
    reset_bar<<<1, 1>>>();

    rnn_persistent<<<NCTA, 256, SMEM_BYTES>>>(x);

    fc_kernel<<<(B_ * T_) / BM, 256, SMEM_BYTES>>>(pred, Wfc, bfc);
    write_hn<<<(B_ * UNITS + 255) / 256, 256>>>(hn);
}

// round 6
// speedup vs baseline: 2.0769x; 2.0769x over previous
#include <cuda_runtime.h>
#include <cuda_fp16.h>
#include <math.h>
#include <stdint.h>

// ---------------- problem dims ----------------
#define B_    512
#define T_    128
#define IDIM  512
#define N0    538
#define N1    358
#define N2    128
#define OUT_  128
#define UNITS 1024

// padded fp16 layouts (all K segments multiples of 32; h strides padded)
#define NP0   2176      // 4*538=2152 -> 17*128
#define KP0   1088      // [x 512 | h0 538->576]
#define NP1   1536      // 4*358=1432 -> 12*128
#define KP1   960       // [h0 576 | h1 358->384]
#define NP2   512       // 4*128
#define KP2   512       // [h1 384 | h2 128]
#define LH0   576
#define LH1   384
#define LH2   128

#define NCTA  132       // 68 L0 + 48 L1 + 16 L2

// tile config: CTA 128x128, BK=32 (two k16 steps), fp16 operands
#define LDA     40                  // halfs per smem row (80B -> conflict-free ldmatrix)
#define STAGEH  (128*LDA)           // halfs per stage matrix (5120 -> 10240 B)
#define LDC     132
#define SMEM_DYN 69632              // >= max(4*10240=40960, Cs=128*132*4=67584) + align slack

// ---------------- device globals ----------------
__device__ __align__(16) __half g_x16[(size_t)B_ * T_ * IDIM];
__device__ __align__(16) __half g_w0[(size_t)NP0 * KP0];
__device__ __align__(16) __half g_w1[(size_t)NP1 * KP1];
__device__ __align__(16) __half g_w2[(size_t)NP2 * KP2];
__device__ __align__(16) float  g_bc0[NP0];
__device__ __align__(16) float  g_bc1[NP1];
__device__ __align__(16) float  g_bc2[NP2];
__device__ __align__(16) __half g_h16_0[2][B_ * LH0];
__device__ __align__(16) __half g_h16_1[2][B_ * LH1];
__device__ __align__(16) __half g_h16_2[2][B_ * LH2];
__device__ __align__(16) float  g_h32_0[B_ * N0];
__device__ __align__(16) float  g_h32_1[B_ * N1];
__device__ __align__(16) float  g_h32_2[B_ * N2];
__device__ __align__(16) float  g_motor[(size_t)B_ * T_ * OUT_];
__device__ unsigned g_bar_count;
__device__ unsigned g_bar_release;

// ---------------- PTX helpers ----------------
__device__ __forceinline__ uint32_t s2u(const void* p) {
    return (uint32_t)__cvta_generic_to_shared(p);
}
__device__ __forceinline__ void cpa16(uint32_t dst, const void* src) {
    asm volatile("cp.async.cg.shared.global [%0], [%1], 16;"
                 :: "r"(dst), "l"(src) : "memory");
}
#define CP_COMMIT() asm volatile("cp.async.commit_group;" ::: "memory")

__device__ __forceinline__ void ldsm_x4(uint32_t& r0, uint32_t& r1, uint32_t& r2, uint32_t& r3,
                                        uint32_t addr)
{
    asm volatile("ldmatrix.sync.aligned.m8n8.x4.shared.b16 {%0,%1,%2,%3}, [%4];"
                 : "=r"(r0), "=r"(r1), "=r"(r2), "=r"(r3) : "r"(addr));
}
__device__ __forceinline__ void mma_f16(float& c0, float& c1, float& c2, float& c3,
                                        uint32_t a0, uint32_t a1, uint32_t a2, uint32_t a3,
                                        uint32_t b0, uint32_t b1)
{
    asm volatile("mma.sync.aligned.m16n8k16.row.col.f32.f16.f16.f32 "
                 "{%0,%1,%2,%3}, {%4,%5,%6,%7}, {%8,%9}, {%0,%1,%2,%3};"
                 : "+f"(c0), "+f"(c1), "+f"(c2), "+f"(c3)
                 : "r"(a0), "r"(a1), "r"(a2), "r"(a3), "r"(b0), "r"(b1));
}

// ---------------- prep kernels ----------------
__global__ void cvt_x(const float* __restrict__ x)
{
    size_t i = (size_t)blockIdx.x * blockDim.x + threadIdx.x;
    size_t n2 = (size_t)B_ * T_ * IDIM / 2;
    if (i < n2) {
        float2 v = ((const float2*)x)[i];
        ((__half2*)g_x16)[i] = __floats2half2_rn(v.x, v.y);
    }
}

// masked interleaved fp16 weights + padded fp32 bias
__global__ void build_w16(const float* __restrict__ W1, const float* __restrict__ W2,
                          const float* __restrict__ Wa, const float* __restrict__ Wb,
                          const float* __restrict__ mask,
                          const float* __restrict__ b1, const float* __restrict__ b2,
                          const float* __restrict__ ba, const float* __restrict__ bb,
                          __half* __restrict__ Wc, float* __restrict__ bc,
                          int n, int Korig, int k1real, int k1pad, int KP, int NP)
{
    int idx = blockIdx.x * blockDim.x + threadIdx.x;
    if (idx < NP * KP) {
        int row = idx / KP, kp = idx - row * KP;
        float v = 0.f;
        if (row < 4 * n) {
            int kk = -1;
            if (kp < k1real) kk = kp;
            else if (kp >= k1pad && kp < k1pad + (Korig - k1real)) kk = k1real + (kp - k1pad);
            if (kk >= 0) {
                int j = row >> 2, g = row & 3;
                if (g == 0)      v = W1[(size_t)j * Korig + kk] * mask[(size_t)j * Korig + kk];
                else if (g == 1) v = W2[(size_t)j * Korig + kk] * mask[(size_t)j * Korig + kk];
                else if (g == 2) v = Wa[(size_t)j * Korig + kk];
                else             v = Wb[(size_t)j * Korig + kk];
            }
        }
        Wc[idx] = __float2half_rn(v);
    }
    if (idx < NP) {
        float v = 0.f;
        if (idx < 4 * n) {
            int j = idx >> 2, g = idx & 3;
            v = (g == 0) ? b1[j] : (g == 1) ? b2[j] : (g == 2) ? ba[j] : bb[j];
        }
        bc[idx] = v;
    }
}

__global__ void zero_h16()
{
    int i = blockIdx.x * blockDim.x + threadIdx.x;
    __half2 z = __half2half2(__float2half(0.f));
    if (i < 2 * B_ * LH0 / 2) ((__half2*)g_h16_0)[i] = z;
    if (i < 2 * B_ * LH1 / 2) ((__half2*)g_h16_1)[i] = z;
    if (i < 2 * B_ * LH2 / 2) ((__half2*)g_h16_2)[i] = z;
}

__global__ void fill_h16(const float* __restrict__ h0in)
{
    int idx = blockIdx.x * blockDim.x + threadIdx.x;
    if (idx >= B_ * UNITS) return;
    int b = idx / UNITS, c = idx - b * UNITS;
    __half v = __float2half_rn(h0in[idx]);
    if (c < N0)           g_h16_0[0][b * LH0 + c] = v;
    else if (c < N0 + N1) g_h16_1[0][b * LH1 + (c - N0)] = v;
    else                  g_h16_2[0][b * LH2 + (c - N0 - N1)] = v;
}

__global__ void write_hn(float* __restrict__ out)
{
    int idx = blockIdx.x * blockDim.x + threadIdx.x;
    if (idx >= B_ * UNITS) return;
    int b = idx / UNITS, c = idx - b * UNITS;
    float v;
    if (c < N0)           v = g_h32_0[b * N0 + c];
    else if (c < N0 + N1) v = g_h32_1[b * N1 + (c - N0)];
    else                  v = g_h32_2[b * N2 + (c - N0 - N1)];
    out[idx] = v;
}

__global__ void reset_bar() { g_bar_count = 0; g_bar_release = 0; }

// ---------------- grid barrier ----------------
__device__ __forceinline__ void grid_bar(int epoch)
{
    __syncthreads();
    if (threadIdx.x == 0) {
        __threadfence();
        unsigned a = atomicAdd(&g_bar_count, 1u) + 1u;
        if (a == (unsigned)(NCTA * epoch)) {
            asm volatile("st.global.release.gpu.u32 [%0], %1;"
                         :: "l"(&g_bar_release), "r"((unsigned)epoch) : "memory");
        } else {
            unsigned r;
            do {
                asm volatile("ld.global.acquire.gpu.u32 %0, [%1];"
                             : "=r"(r) : "l"(&g_bar_release) : "memory");
            } while (r < (unsigned)epoch);
        }
    }
    __syncthreads();
}

// ---------------- A segment base per (layer,t,kc32), m0 applied ----------------
__device__ __forceinline__ const __half* a_base(int layer, int t, int kc, int m0, int& stride)
{
    if (layer == 0) {
        if (kc < 16) { stride = T_ * IDIM; return g_x16 + (size_t)m0 * (T_ * IDIM) + (size_t)t * IDIM + kc * 32; }
        stride = LH0; return g_h16_0[t & 1] + (size_t)m0 * LH0 + (kc - 16) * 32;
    } else if (layer == 1) {
        if (kc < 18) { stride = LH0; return g_h16_0[1 - (t & 1)] + (size_t)m0 * LH0 + kc * 32; }
        stride = LH1; return g_h16_1[t & 1] + (size_t)m0 * LH1 + (kc - 18) * 32;
    } else {
        if (kc < 12) { stride = LH1; return g_h16_1[1 - (t & 1)] + (size_t)m0 * LH1 + kc * 32; }
        stride = LH2; return g_h16_2[t & 1] + (size_t)m0 * LH2 + (kc - 12) * 32;
    }
}

// ---------------- one tile: fp16 ldmatrix/mma GEMM + fused CfC gate ----------------
__device__ void run_tile(int layer, int t, int m0, int n0, char* smbase)
{
    const __half* wbase; const float* bias; int KP, nkt;
    if (layer == 0)      { wbase = g_w0; bias = g_bc0; KP = KP0; nkt = KP0 / 32; }
    else if (layer == 1) { wbase = g_w1; bias = g_bc1; KP = KP1; nkt = KP1 / 32; }
    else                 { wbase = g_w2; bias = g_bc2; KP = KP2; nkt = KP2 / 32; }

    const uint32_t sm_u32 = s2u(smbase);
    const int tid  = threadIdx.x;
    const int lane = tid & 31;
    const int wid  = tid >> 5;
    const int wm   = wid & 1;        // 2 warps in M (64 rows each)
    const int wn   = wid >> 1;       // 4 warps in N (32 cols each)

    float acc[4][4][4];
    #pragma unroll
    for (int mt = 0; mt < 4; mt++)
        #pragma unroll
        for (int nt = 0; nt < 4; nt++)
            #pragma unroll
            for (int i = 0; i < 4; i++) acc[mt][nt][i] = 0.f;

    auto fill = [&](int kc) {
        int s = kc & 1;
        uint32_t a_s = sm_u32 + s * (STAGEH * 2);
        uint32_t b_s = sm_u32 + 2 * (STAGEH * 2) + s * (STAGEH * 2);
        int astr; const __half* ab = a_base(layer, t, kc, m0, astr);
        const __half* wb = wbase + (size_t)n0 * KP + kc * 32;
        #pragma unroll
        for (int i = 0; i < 2; i++) {
            int u = tid + i * 256;
            int r = u >> 2, q = u & 3;
            cpa16(a_s + r * 80 + q * 16, ab + (size_t)r * astr + q * 8);
            cpa16(b_s + r * 80 + q * 16, wb + (size_t)r * KP + q * 8);
        }
        CP_COMMIT();
    };

    fill(0);

    for (int kt = 0; kt < nkt; kt++) {
        __syncthreads();   // everyone done reading the buffer we are about to refill
        if (kt + 1 < nkt) fill(kt + 1);
        if (kt + 1 < nkt) asm volatile("cp.async.wait_group 1;" ::: "memory");
        else              asm volatile("cp.async.wait_group 0;" ::: "memory");
        __syncthreads();

        int buf = kt & 1;
        uint32_t a_s = sm_u32 + buf * (STAGEH * 2);
        uint32_t b_s = sm_u32 + 2 * (STAGEH * 2) + buf * (STAGEH * 2);

        #pragma unroll
        for (int ks = 0; ks < 32; ks += 16) {
            uint32_t af[4][4], bf[4][2];
            // A fragments: 4 m16 tiles, ldmatrix.x4 each
            #pragma unroll
            for (int mt = 0; mt < 4; mt++) {
                int row = wm * 64 + mt * 16 + (lane & 15);
                uint32_t addr = a_s + row * 80 + ks * 2 + (lane >> 4) * 16;
                ldsm_x4(af[mt][0], af[mt][1], af[mt][2], af[mt][3], addr);
            }
            // B fragments: 4 n8 tiles, 2x ldmatrix.x4 (each covers 2 n-tiles x k16)
            #pragma unroll
            for (int j = 0; j < 2; j++) {
                int q = lane >> 3;
                int row = wn * 32 + 16 * j + (q >> 1) * 8 + (lane & 7);
                uint32_t addr = b_s + row * 80 + (ks + (q & 1) * 8) * 2;
                ldsm_x4(bf[2 * j][0], bf[2 * j][1], bf[2 * j + 1][0], bf[2 * j + 1][1], addr);
            }
            #pragma unroll
            for (int mt = 0; mt < 4; mt++)
                #pragma unroll
                for (int nt = 0; nt < 4; nt++)
                    mma_f16(acc[mt][nt][0], acc[mt][nt][1], acc[mt][nt][2], acc[mt][nt][3],
                            af[mt][0], af[mt][1], af[mt][2], af[mt][3],
                            bf[nt][0], bf[nt][1]);
        }
    }

    // ---- epilogue: stage C in smem (aliases A/B buffers), then gate ----
    __syncthreads();
    float* Cs = (float*)smbase;   // [128][LDC]
    {
        int g = lane >> 2, tk = lane & 3;
        #pragma unroll
        for (int mt = 0; mt < 4; mt++) {
            int row = wm * 64 + mt * 16 + g;
            #pragma unroll
            for (int nt = 0; nt < 4; nt++) {
                int col = wn * 32 + nt * 8 + 2 * tk;
                Cs[row * LDC + col]           = acc[mt][nt][0];
                Cs[row * LDC + col + 1]       = acc[mt][nt][1];
                Cs[(row + 8) * LDC + col]     = acc[mt][nt][2];
                Cs[(row + 8) * LDC + col + 1] = acc[mt][nt][3];
            }
        }
    }
    __syncthreads();

    // outputs
    __half* h16; int ldh;
    float *f1 = nullptr, *f2 = nullptr; int ldf1 = 0, ldf2 = 0, n1 = 0, nr2 = 0;
    int wp = 1 - (t & 1);
    bool last = (t == T_ - 1);
    if (layer == 0) {
        h16 = g_h16_0[wp]; ldh = LH0;
        if (last) { f1 = g_h32_0; ldf1 = N0; n1 = N0; }
    } else if (layer == 1) {
        h16 = g_h16_1[wp]; ldh = LH1;
        if (last) { f1 = g_h32_1; ldf1 = N1; n1 = N1; }
    } else {
        h16 = g_h16_2[wp]; ldh = LH2;
        f1 = g_motor + (size_t)t * OUT_; ldf1 = T_ * OUT_; n1 = N2;
        if (last) { f2 = g_h32_2; ldf2 = N2; nr2 = N2; }
    }

    {
        int ul = tid & 31;
        int u  = (n0 >> 2) + ul;
        float4 bb = *(const float4*)(bias + 4 * u);
        #pragma unroll
        for (int r = 0; r < 16; r++) {
            int row = (tid >> 5) + 8 * r;
            float4 v = *(const float4*)(Cs + row * LDC + 4 * ul);
            float ff1 = tanhf(v.x + bb.x);
            float ff2 = tanhf(v.y + bb.y);
            float s   = (v.z + bb.z) + (v.w + bb.w);
            float tg  = 1.f / (1.f + __expf(-s));
            float h   = ff1 + tg * (ff2 - ff1);
            size_t grow = (size_t)(m0 + row);
            h16[grow * ldh + u] = __float2half_rn(h);
            if (f1 && u < n1)  f1[grow * ldf1 + u] = h;
            if (f2 && u < nr2) f2[grow * ldf2 + u] = h;
        }
    }
    __syncthreads();   // protect smem before next phase reuses it
}

// ---------------- persistent wavefront kernel ----------------
__global__ __launch_bounds__(256, 1)
void rnn_f16()
{
    extern __shared__ char smraw[];
    char* smbase = (char*)(((uintptr_t)smraw + 127) & ~(uintptr_t)127);
    const int bid = blockIdx.x;

    int layer, mrow, ncol;
    if (bid < 68)       { layer = 0; mrow = bid & 3; ncol = bid >> 2; }
    else if (bid < 116) { layer = 1; int b = bid - 68;  mrow = b & 3; ncol = b >> 2; }
    else                { layer = 2; int b = bid - 116; mrow = b & 3; ncol = b >> 2; }

    for (int p = 0; p < T_ + 2; p++) {
        int t = p - layer;
        if (t >= 0 && t < T_)
            run_tile(layer, t, mrow * 128, ncol * 128, smbase);
        grid_bar(p + 1);
    }
}

// ================= tf32 path for the final FC (verified in R2/R3) =================
#define BMF 128
#define BKF 32
#define LDKF 36
#define LDCF 132
#define SMEM_FC (4*BMF*LDKF*4)

__device__ __forceinline__ float f2tf32(float f) {
    unsigned r;
    asm("cvt.rna.tf32.f32 %0, %1;" : "=r"(r) : "f"(f));
    return __uint_as_float(r);
}
__device__ __forceinline__ void mma_tf32(float& c0, float& c1, float& c2, float& c3,
                                         unsigned a0, unsigned a1, unsigned a2, unsigned a3,
                                         unsigned b0, unsigned b1)
{
    asm volatile("mma.sync.aligned.m16n8k8.row.col.f32.tf32.tf32.f32 "
                 "{%0,%1,%2,%3}, {%4,%5,%6,%7}, {%8,%9}, {%0,%1,%2,%3};"
                 : "+f"(c0), "+f"(c1), "+f"(c2), "+f"(c3)
                 : "r"(a0), "r"(a1), "r"(a2), "r"(a3), "r"(b0), "r"(b1));
}

__global__ __launch_bounds__(256)
void fc_kernel(float* __restrict__ pred, const float* __restrict__ Wfc,
               const float* __restrict__ bfc)
{
    extern __shared__ float sm[];
    float* As = sm;
    float* Bs = sm + 2 * BMF * LDKF;

    const float* A = g_motor;
    const int Ktot = OUT_, KP = 128, Nout = OUT_;

    const int tid  = threadIdx.x;
    const int lane = tid & 31;
    const int g    = lane >> 2;
    const int tk   = lane & 3;
    const int wid  = tid >> 5;
    const int wm   = wid & 1;
    const int wn   = wid >> 1;
    const int m0   = blockIdx.x * BMF;

    const int lK  = tid & 31;
    const int arb = tid >> 5;
    const int bkg = (tid & 7) * 4;
    const int bnb = tid >> 3;

    float acc[4][4][4];
    #pragma unroll
    for (int mt = 0; mt < 4; mt++)
        #pragma unroll
        for (int nt = 0; nt < 4; nt++)
            #pragma unroll
            for (int i = 0; i < 4; i++) acc[mt][nt][i] = 0.f;

    const int nkt = KP / BKF;
    float areg[16]; float4 breg[4];

    auto ldg = [&](int kt) {
        int k = kt * BKF + lK;
        #pragma unroll
        for (int r = 0; r < 16; r++)
            areg[r] = A[(size_t)(m0 + arb + r * 8) * Ktot + k];
        int kb = kt * BKF + bkg;
        #pragma unroll
        for (int r = 0; r < 4; r++)
            breg[r] = *(const float4*)(Wfc + (size_t)(bnb + r * 32) * Ktot + kb);
    };
    auto sts = [&](int buf) {
        float* a = As + buf * BMF * LDKF;
        float* b = Bs + buf * BMF * LDKF;
        #pragma unroll
        for (int r = 0; r < 16; r++) a[(arb + r * 8) * LDKF + lK] = f2tf32(areg[r]);
        #pragma unroll
        for (int r = 0; r < 4; r++) {
            float4 v = breg[r];
            v.x = f2tf32(v.x); v.y = f2tf32(v.y); v.z = f2tf32(v.z); v.w = f2tf32(v.w);
            *(float4*)(b + (bnb + r * 32) * LDKF + bkg) = v;
        }
    };

    ldg(0); sts(0); __syncthreads();

    for (int kt = 0; kt < nkt; kt++) {
        if (kt + 1 < nkt) ldg(kt + 1);
        const float* a = As + (kt & 1) * BMF * LDKF;
        const float* b = Bs + (kt & 1) * BMF * LDKF;
        #pragma unroll
        for (int ks = 0; ks < BKF; ks += 8) {
            unsigned af[4][4], bf[4][2];
            #pragma unroll
            for (int mt = 0; mt < 4; mt++) {
                int row = wm * 64 + mt * 16 + g;
                af[mt][0] = __float_as_uint(a[row * LDKF + ks + tk]);
                af[mt][1] = __float_as_uint(a[(row + 8) * LDKF + ks + tk]);
                af[mt][2] = __float_as_uint(a[row * LDKF + ks + tk + 4]);
                af[mt][3] = __float_as_uint(a[(row + 8) * LDKF + ks + tk + 4]);
            }
            #pragma unroll
            for (int nt = 0; nt < 4; nt++) {
                int n = wn * 32 + nt * 8 + g;
                bf[nt][0] = __float_as_uint(b[n * LDKF + ks + tk]);
                bf[nt][1] = __float_as_uint(b[n * LDKF + ks + tk + 4]);
            }
            #pragma unroll
            for (int mt = 0; mt < 4; mt++)
                #pragma unroll
                for (int nt = 0; nt < 4; nt++)
                    mma_tf32(acc[mt][nt][0], acc[mt][nt][1], acc[mt][nt][2], acc[mt][nt][3],
                             af[mt][0], af[mt][1], af[mt][2], af[mt][3],
                             bf[nt][0], bf[nt][1]);
        }
        if (kt + 1 < nkt) { sts((kt + 1) & 1); __syncthreads(); }
    }

    __syncthreads();
    float* Cs = sm;
    #pragma unroll
    for (int mt = 0; mt < 4; mt++) {
        int row = wm * 64 + mt * 16 + g;
        #pragma unroll
        for (int nt = 0; nt < 4; nt++) {
            int col = wn * 32 + nt * 8 + 2 * tk;
            Cs[row * LDCF + col]           = acc[mt][nt][0];
            Cs[row * LDCF + col + 1]       = acc[mt][nt][1];
            Cs[(row + 8) * LDCF + col]     = acc[mt][nt][2];
            Cs[(row + 8) * LDCF + col + 1] = acc[mt][nt][3];
        }
    }
    __syncthreads();

    int ul  = tid & 31;
    int col = 4 * ul;
    float4 bb = *(const float4*)(bfc + col);
    #pragma unroll
    for (int r = 0; r < 16; r++) {
        int row = (tid >> 5) + 8 * r;
        float4 v = *(const float4*)(Cs + row * LDCF + col);
        v.x += bb.x; v.y += bb.y; v.z += bb.z; v.w += bb.w;
        *(float4*)(pred + (size_t)(m0 + row) * Nout + col) = v;
    }
}

// ---------------- launcher ----------------
extern "C" void kernel_launch(void* const* d_in, const int* in_sizes, int n_in,
                              void* d_out, int out_size)
{
    (void)in_sizes; (void)n_in; (void)out_size;
    const float* x    = (const float*)d_in[0];
    const float* h0in = (const float*)d_in[1];
    const float* mask[3]  = { (const float*)d_in[2],  (const float*)d_in[11], (const float*)d_in[20] };
    const float* Wff1[3]  = { (const float*)d_in[3],  (const float*)d_in[12], (const float*)d_in[21] };
    const float* Wff2[3]  = { (const float*)d_in[4],  (const float*)d_in[13], (const float*)d_in[22] };
    const float* Wta[3]   = { (const float*)d_in[5],  (const float*)d_in[14], (const float*)d_in[23] };
    const float* Wtb[3]   = { (const float*)d_in[6],  (const float*)d_in[15], (const float*)d_in[24] };
    const float* bff1[3]  = { (const float*)d_in[7],  (const float*)d_in[16], (const float*)d_in[25] };
    const float* bff2[3]  = { (const float*)d_in[8],  (const float*)d_in[17], (const float*)d_in[26] };
    const float* bta[3]   = { (const float*)d_in[9],  (const float*)d_in[18], (const float*)d_in[27] };
    const float* btb[3]   = { (const float*)d_in[10], (const float*)d_in[19], (const float*)d_in[28] };
    const float* Wfc = (const float*)d_in[29];
    const float* bfc = (const float*)d_in[30];

    float* out  = (float*)d_out;
    float* pred = out;
    float* hn   = out + (size_t)B_ * T_ * OUT_;

    cudaFuncSetAttribute(rnn_f16,   cudaFuncAttributeMaxDynamicSharedMemorySize, SMEM_DYN);
    cudaFuncSetAttribute(fc_kernel, cudaFuncAttributeMaxDynamicSharedMemorySize, SMEM_FC);

    __half* dW16[3]; float* dbc[3];
    cudaGetSymbolAddress((void**)&dW16[0], g_w0);
    cudaGetSymbolAddress((void**)&dW16[1], g_w1);
    cudaGetSymbolAddress((void**)&dW16[2], g_w2);
    cudaGetSymbolAddress((void**)&dbc[0], g_bc0);
    cudaGetSymbolAddress((void**)&dbc[1], g_bc1);
    cudaGetSymbolAddress((void**)&dbc[2], g_bc2);

    {   // x -> fp16
        size_t n2 = (size_t)B_ * T_ * IDIM / 2;
        cvt_x<<<(unsigned)((n2 + 255) / 256), 256>>>(x);
    }
    {
        int tot = NP0 * KP0;
        build_w16<<<(tot + 255) / 256, 256>>>(Wff1[0], Wff2[0], Wta[0], Wtb[0], mask[0],
                                              bff1[0], bff2[0], bta[0], btb[0],
                                              dW16[0], dbc[0], N0, 1050, 512, 512, KP0, NP0);
    }
    {
        int tot = NP1 * KP1;
        build_w16<<<(tot + 255) / 256, 256>>>(Wff1[1], Wff2[1], Wta[1], Wtb[1], mask[1],
                                              bff1[1], bff2[1], bta[1], btb[1],
                                              dW16[1], dbc[1], N1, 896, 538, 576, KP1, NP1);
    }
    {
        int tot = NP2 * KP2;
        build_w16<<<(tot + 255) / 256, 256>>>(Wff1[2], Wff2[2], Wta[2], Wtb[2], mask[2],
                                              bff1[2], bff2[2], bta[2], btb[2],
                                              dW16[2], dbc[2], N2, 486, 358, 384, KP2, NP2);
    }
    zero_h16<<<(2 * B_ * LH0 / 2 + 255) / 256, 256>>>();
    fill_h16<<<(B_ * UNITS + 255) / 256, 256>>>(h0in);
    reset_bar<<<1, 1>>>();

    rnn_f16<<<NCTA, 256, SMEM_DYN>>>();

    fc_kernel<<<(B_ * T_) / BMF, 256, SMEM_FC>>>(pred, Wfc, bfc);
    write_hn<<<(B_ * UNITS + 255) / 256, 256>>>(hn);
}